// round 16
// baseline (speedup 1.0000x reference)
#include <cuda_runtime.h>
#include <cuda_fp16.h>
#include <cstdint>

// IsokawaPytorchLayer as fp16 mma.sync GEMM (HMMA; tcgen05 is sm_103a-gated and
// the harness builds compute_103):
//   out[b, 4n+c] = sigmoid( sum_k X[b,k] * W[4n+c, k] )
// with X[b,0] := 1 and W[:,0] := -theta (x w-component == 0 makes col 0 free).
// R15: register-budget-safe version of R14's two ideas. (1) producer prefetch
// depth 16 (64 regs, two half-batches) instead of 32 (128 regs -> spilled at
// the 255-reg cap in R14); (2) fused B build kept but #pragma unroll 1 so the
// prologue doesn't inflate the common-path register allocation.

#define NDIM  256
#define MTILE 64
#define NTHR  256

#define SM_A0 0
#define SM_A1 32768
#define SM_B  65536
#define SM_TOTAL (65536 + 131072)

// Left Hamilton matrix rows: c0 {w,-x,-y,-z} c1 {x,w,-z,y} c2 {y,z,w,-x} c3 {z,-y,x,w}
__device__ __forceinline__ float qcoef(float4 q, int c, int d) {
    float v = 0.0f;
    if (c == 0) v = (d == 0) ? q.x : (d == 1) ? -q.y : (d == 2) ? -q.z : -q.w;
    if (c == 1) v = (d == 0) ? q.y : (d == 1) ?  q.x : (d == 2) ? -q.w :  q.z;
    if (c == 2) v = (d == 0) ? q.z : (d == 1) ?  q.w : (d == 2) ?  q.x : -q.y;
    if (c == 3) v = (d == 0) ? q.w : (d == 1) ? -q.z : (d == 2) ?  q.y :  q.x;
    return v;
}

// sigmoid(s) = 0.5 + 0.5*tanh(s/2): one MUFU.TANH + FFMA.
__device__ __forceinline__ float sigm(float s) {
    float r;
    asm("tanh.approx.f32 %0, %1;" : "=f"(r) : "f"(s * 0.5f));
    return fmaf(0.5f, r, 0.5f);
}

// Build W fragment chunk t (16B) directly into smem B region.
// Layout: chunk t = [ks][ngroup][jb][lane]. COLUMN PERMUTATION: fragment
// (f = 2*jb+s), n-within-frag v = lane>>2 maps to physical row
//   ngp*64 + 16*jb + 4*(v>>1) + 2*s + (v&1)
// so the epilogue's 4 values per lane are consecutive output cols (STG.128).
__device__ __noinline__ void build_b_chunk(unsigned char* Bsm, int t,
                                           const float4* __restrict__ wg,
                                           const float4* __restrict__ tg) {
    int lane = t & 31, jb = (t >> 5) & 3, ngp = (t >> 7) & 3, ks = t >> 9;
    __half h[8];
    #pragma unroll
    for (int s = 0; s < 2; s++) {
        int v  = lane >> 2;
        int rr = ngp * 64 + 16 * jb + 4 * (v >> 1) + 2 * s + (v & 1);
        int n = rr >> 2, c = rr & 3;
        int k0 = ks * 16 + 2 * (lane & 3);
        int kk[4] = {k0, k0 + 1, k0 + 8, k0 + 9};
        #pragma unroll
        for (int i = 0; i < 4; i++) {
            int k = kk[i], m = k >> 2, d = k & 3;
            float4 q = wg[n * 64 + m];
            float vv = qcoef(q, c, d);
            if (k == 0) {
                float4 th = tg[n];
                vv = -((c == 0) ? th.x : (c == 1) ? th.y : (c == 2) ? th.z : th.w);
            }
            h[s * 4 + i] = __float2half_rn(vv);
        }
    }
    *(uint4*)(Bsm + t * 16) = *(const uint4*)h;
}

// Producer half-batch: 16 LDG.128 issued back-to-back (8KB/warp-group in
// flight), then cvt + XOR-swizzled STS. Chunk contract (consumer reads 16B
// chunk (lane^ks) of block (r>>4)&3):
//   x=(r,kA) y=(r+8,kA) z=(r,kA+8) w=(r+8,kA+8), kA = 16*ks + 2*(L&3).
__device__ __forceinline__ void stage_half(unsigned char* Ab, const float4* xt,
                                           int kq, int rb2, int i0) {
    const int ks  = kq >> 2;
    const int sub = ((kq >> 1) & 1) * 8;
    const int t4  = 2 * (kq & 1);
    float4 pf[16];
    #pragma unroll
    for (int i = 0; i < 16; i++) {
        int r = 2 * (i0 + i) + rb2;
        pf[i] = xt[r * 64 + kq];
    }
    #pragma unroll
    for (int i = 0; i < 16; i++) {
        int r = 2 * (i0 + i) + rb2;
        float4 v = pf[i];
        if (kq == 0) v.x = 1.0f;             // X[b,0] := 1 (xw==0 guaranteed)
        int lane_lo = 4 * (r & 7) + t4;
        int c0 = lane_lo ^ ks;
        int c1 = (lane_lo + 1) ^ ks;
        int base = ks * 2048 + ((r >> 4) & 3) * 512 + ((r >> 3) & 1) * 4 + sub;
        *(__half2*)(Ab + base + c0 * 16) = __floats2half2_rn(v.x, v.y);
        *(__half2*)(Ab + base + c1 * 16) = __floats2half2_rn(v.z, v.w);
    }
}

__device__ __forceinline__ void stage_tile(unsigned char* Ab, const float4* xt,
                                           int kq, int rb2) {
    stage_half(Ab, xt, kq, rb2, 0);
    stage_half(Ab, xt, kq, rb2, 16);
}

// Persistent GEMM. Warps 0..3: consumers, warp tile 64x64 (ng = warp id).
// Warps 4..7: producers (stage tile t+grid while consumers work on t).
extern "C" __global__ void __launch_bounds__(NTHR, 1)
gemm_kernel(const float4* __restrict__ xg,
            const float4* __restrict__ wg,
            const float4* __restrict__ tg,
            float* __restrict__ out, int ntiles)
{
    extern __shared__ unsigned char smem[];
    const int tid = threadIdx.x;

    // ---- build B in-place (fragment-ready + column permutation) ----
    // unroll 1: keep prologue live-range tiny so it can't inflate the
    // kernel-wide register allocation (R14's spill source).
    {
        unsigned char* Bsm = smem + SM_B;
        #pragma unroll 1
        for (int i = 0; i < 32; i++)
            build_b_chunk(Bsm, i * NTHR + tid, wg, tg);
    }

    const bool is_prod = (tid >= 128);
    int t = blockIdx.x;

    if (is_prod) {
        // ---------------- PRODUCER ----------------
        const int ptid = tid - 128;
        const int kq = ptid & 63, rb2 = ptid >> 6;

        stage_tile(smem + SM_A0, xg + (size_t)t * 4096, kq, rb2);
        __syncthreads();

        int buf = 0;
        while (t < ntiles) {
            const int tn = t + (int)gridDim.x;
            if (tn < ntiles)
                stage_tile(smem + (buf ? SM_A0 : SM_A1),
                           xg + (size_t)tn * 4096, kq, rb2);
            __syncthreads();
            buf ^= 1;
            t = tn;
        }
    } else {
        // ---------------- CONSUMER ----------------
        const int w = tid >> 5, lane = tid & 31;
        const int ng = w;                               // warp tile 64 x 64
        const unsigned char* Bb = smem + SM_B + ng * 2048 + lane * 16;

        __syncthreads();                                // B + buf0 ready

        int buf = 0;
        while (t < ntiles) {
            float acc[4][8][4];
            #pragma unroll
            for (int j = 0; j < 4; j++)
                #pragma unroll
                for (int f = 0; f < 8; f++)
                    #pragma unroll
                    for (int i = 0; i < 4; i++) acc[j][f][i] = 0.0f;

            const unsigned char* A = smem + (buf ? SM_A1 : SM_A0);
            #pragma unroll
            for (int ks = 0; ks < 16; ks++) {
                const int lx = (lane ^ ks) * 16;        // ks-XOR chunk placement
                uint4 a[4];
                #pragma unroll
                for (int j = 0; j < 4; j++)
                    a[j] = *(const uint4*)(A + ks * 2048 + j * 512 + lx);
                uint4 bq[4];
                #pragma unroll
                for (int jb = 0; jb < 4; jb++)
                    bq[jb] = *(const uint4*)(Bb + ks * 8192 + jb * 512);
                #pragma unroll
                for (int j = 0; j < 4; j++) {
                    #pragma unroll
                    for (int f = 0; f < 8; f++) {
                        const uint4& b = bq[f >> 1];
                        uint32_t r0 = (f & 1) ? b.z : b.x;
                        uint32_t r1 = (f & 1) ? b.w : b.y;
                        asm volatile(
                            "mma.sync.aligned.m16n8k16.row.col.f32.f16.f16.f32 "
                            "{%0,%1,%2,%3}, {%4,%5,%6,%7}, {%8,%9}, {%0,%1,%2,%3};"
                            : "+f"(acc[j][f][0]), "+f"(acc[j][f][1]),
                              "+f"(acc[j][f][2]), "+f"(acc[j][f][3])
                            : "r"(a[j].x), "r"(a[j].y), "r"(a[j].z), "r"(a[j].w),
                              "r"(r0), "r"(r1));
                    }
                }
            }

            // epilogue: sigmoid + permuted STG.128 (4 consecutive floats/lane)
            {
                const int q = lane & 3;
                const size_t rowbase = (size_t)t * MTILE + (lane >> 2);
                #pragma unroll
                for (int j = 0; j < 4; j++) {
                    size_t r0 = rowbase + j * 16;
                    #pragma unroll
                    for (int i = 0; i < 4; i++) {
                        int col = ng * 64 + 16 * i + 4 * q;
                        float4 v0, v1;
                        v0.x = sigm(acc[j][2 * i][0]);     v0.y = sigm(acc[j][2 * i][1]);
                        v0.z = sigm(acc[j][2 * i + 1][0]); v0.w = sigm(acc[j][2 * i + 1][1]);
                        v1.x = sigm(acc[j][2 * i][2]);     v1.y = sigm(acc[j][2 * i][3]);
                        v1.z = sigm(acc[j][2 * i + 1][2]); v1.w = sigm(acc[j][2 * i + 1][3]);
                        *(float4*)(out + r0 * NDIM + col)       = v0;
                        *(float4*)(out + (r0 + 8) * NDIM + col) = v1;
                    }
                }
            }

            __syncthreads();    // next buffer staged; current reusable
            buf ^= 1;
            t += (int)gridDim.x;
        }
    }
}

extern "C" void kernel_launch(void* const* d_in, const int* in_sizes, int n_in,
                              void* d_out, int out_size) {
    const float4* xg = (const float4*)d_in[0];   // (B, 64, 4) f32
    const float4* wg = (const float4*)d_in[1];   // (64, 64, 4) f32
    const float4* tg = (const float4*)d_in[2];   // (64, 4) f32
    float* out = (float*)d_out;

    int B = in_sizes[0] / 256;                   // 131072
    int ntiles = B / MTILE;                      // 2048
    int grid = 148;
    if (grid > ntiles) grid = ntiles;

    cudaFuncSetAttribute(gemm_kernel,
                         cudaFuncAttributeMaxDynamicSharedMemorySize, SM_TOTAL);

    gemm_kernel<<<grid, NTHR, SM_TOTAL>>>(xg, wg, tg, out, ntiles);
}

// round 17
// speedup vs baseline: 1.2216x; 1.2216x over previous
#include <cuda_runtime.h>
#include <cuda_fp16.h>
#include <cstdint>

// IsokawaPytorchLayer as fp16 mma.sync GEMM (HMMA; tcgen05 is sm_103a-gated and
// the harness builds compute_103):
//   out[b, 4n+c] = sigmoid( sum_k X[b,k] * W[4n+c, k] )
// with X[b,0] := 1 and W[:,0] := -theta (x w-component == 0 makes col 0 free).
// R16: R13 champion + one change: TWO consumer warps per SMSP (8 consumers,
// warp tile 64x32, acc 64 regs) + 8 producers, 512 threads. Second warp per
// SMSP fills tensor-pipe gaps during LDS waits and the epilogue. Fused B-build
// reverted (both attempts lost); separate build_w kernel restored.

#define NDIM  256
#define MTILE 64
#define NTHR  512

#define SM_A0 0
#define SM_A1 32768
#define SM_B  65536
#define SM_TOTAL (65536 + 131072)

__device__ __align__(16) unsigned char g_Wfrag[131072];

// Left Hamilton matrix rows: c0 {w,-x,-y,-z} c1 {x,w,-z,y} c2 {y,z,w,-x} c3 {z,-y,x,w}
__device__ __forceinline__ float qcoef(float4 q, int c, int d) {
    float v = 0.0f;
    if (c == 0) v = (d == 0) ? q.x : (d == 1) ? -q.y : (d == 2) ? -q.z : -q.w;
    if (c == 1) v = (d == 0) ? q.y : (d == 1) ?  q.x : (d == 2) ? -q.w :  q.z;
    if (c == 2) v = (d == 0) ? q.z : (d == 1) ?  q.w : (d == 2) ?  q.x : -q.y;
    if (c == 3) v = (d == 0) ? q.w : (d == 1) ? -q.z : (d == 2) ?  q.y :  q.x;
    return v;
}

// Build W in fragment-ready layout: chunk t = [ks][ngroup][jb][lane], 16 bytes.
// COLUMN PERMUTATION (same as R13): fragment (f = 2*jb+s), v = lane>>2 maps to
// physical row ngp*64 + 16*jb + 4*(v>>1) + 2*s + (v&1), so each epilogue lane's
// 4 values are consecutive output cols (STG.128).
__global__ void build_w(const float4* __restrict__ wg,   // [64*64] (ww,wx,wy,wz)
                        const float4* __restrict__ tg)   // [64] theta
{
    int t = blockIdx.x * blockDim.x + threadIdx.x;       // 0..8191 chunk id
    int lane = t & 31, jb = (t >> 5) & 3, ngp = (t >> 7) & 3, ks = t >> 9;

    __half h[8];
    #pragma unroll
    for (int s = 0; s < 2; s++) {
        int v  = lane >> 2;
        int rr = ngp * 64 + 16 * jb + 4 * (v >> 1) + 2 * s + (v & 1);
        int n = rr >> 2, c = rr & 3;
        int k0 = ks * 16 + 2 * (lane & 3);
        int kk[4] = {k0, k0 + 1, k0 + 8, k0 + 9};
        #pragma unroll
        for (int i = 0; i < 4; i++) {
            int k = kk[i], m = k >> 2, d = k & 3;
            float4 q = wg[n * 64 + m];
            float vv = qcoef(q, c, d);
            if (k == 0) {
                float4 th = tg[n];
                vv = -((c == 0) ? th.x : (c == 1) ? th.y : (c == 2) ? th.z : th.w);
            }
            h[s * 4 + i] = __float2half_rn(vv);
        }
    }
    *(uint4*)(g_Wfrag + t * 16) = *(const uint4*)h;
}

// sigmoid(s) = 0.5 + 0.5*tanh(s/2): one MUFU.TANH + FFMA.
__device__ __forceinline__ float sigm(float s) {
    float r;
    asm("tanh.approx.f32 %0, %1;" : "=f"(r) : "f"(s * 0.5f));
    return fmaf(0.5f, r, 0.5f);
}

// Producer (R12-verified): thread role (kq = f32-quad col, rb4 = row mod 4).
// Row r = 4*it + rb4. Chunk contract (consumer reads chunk (lane^ks) of block
// (r>>4)&3): x=(r,kA) y=(r+8,kA) z=(r,kA+8) w=(r+8,kA+8), kA = 16*ks+2*(L&3).
__device__ __forceinline__ void load8(float4* pf, const float4* xt, int it0,
                                      int rb4, int kq) {
    #pragma unroll
    for (int i = 0; i < 8; i++) {
        int r = 4 * (it0 + i) + rb4;
        pf[i] = xt[r * 64 + kq];
    }
}

__device__ __forceinline__ void stage8(unsigned char* Abuf, const float4* pf,
                                       int it0, int rb4, int kq) {
    const int ks  = kq >> 2;
    const int sub = ((kq >> 1) & 1) * 8;
    const int t4  = 2 * (kq & 1);
    #pragma unroll
    for (int i = 0; i < 8; i++) {
        int r = 4 * (it0 + i) + rb4;
        float4 v = pf[i];
        if (kq == 0) v.x = 1.0f;                 // X[b,0] := 1 (xw==0 guaranteed)
        int lane_lo = 4 * (r & 7) + t4;
        int c0 = lane_lo ^ ks;
        int c1 = (lane_lo + 1) ^ ks;
        int base = ks * 2048 + ((r >> 4) & 3) * 512 + ((r >> 3) & 1) * 4 + sub;
        *(__half2*)(Abuf + base + c0 * 16) = __floats2half2_rn(v.x, v.y);
        *(__half2*)(Abuf + base + c1 * 16) = __floats2half2_rn(v.z, v.w);
    }
}

// Persistent GEMM. Warps 0..7: consumers, warp tile 64 rows x 32 cols
// (ngp = w>>1 picks 64-col group, half = w&1 picks 32-col half -> 2 SMSP-mates
// share an SMSP and interleave). Warps 8..15: producers.
extern "C" __global__ void __launch_bounds__(NTHR, 1)
gemm_kernel(const float4* __restrict__ xg, float* __restrict__ out, int ntiles)
{
    extern __shared__ unsigned char smem[];
    const int tid = threadIdx.x;

    // ---- load B once (fragment-ready, all 512 threads) ----
    {
        const uint4* wb = (const uint4*)g_Wfrag;
        uint4* sb = (uint4*)(smem + SM_B);
        #pragma unroll
        for (int i = 0; i < 16; i++) sb[tid + i * NTHR] = wb[tid + i * NTHR];
    }

    const bool is_prod = (tid >= 256);
    int t = blockIdx.x;

    if (is_prod) {
        // ---------------- PRODUCER ----------------
        const int ptid = tid - 256;
        const int kq = ptid & 63, rb4 = ptid >> 6;
        float4 pf[8];

        {
            const float4* xt = xg + (size_t)t * 4096;
            load8(pf, xt, 0, rb4, kq);
            stage8(smem + SM_A0, pf, 0, rb4, kq);
            load8(pf, xt, 8, rb4, kq);
            stage8(smem + SM_A0, pf, 8, rb4, kq);
        }
        __syncthreads();

        int buf = 0;
        while (t < ntiles) {
            const int tn = t + (int)gridDim.x;
            if (tn < ntiles) {
                unsigned char* Ab = smem + (buf ? SM_A0 : SM_A1);
                const float4* xt = xg + (size_t)tn * 4096;
                load8(pf, xt, 0, rb4, kq);
                stage8(Ab, pf, 0, rb4, kq);
                load8(pf, xt, 8, rb4, kq);
                stage8(Ab, pf, 8, rb4, kq);
            }
            __syncthreads();
            buf ^= 1;
            t = tn;
        }
    } else {
        // ---------------- CONSUMER ----------------
        const int w = tid >> 5, lane = tid & 31;
        const int ngp = w >> 1, half = w & 1;           // 64-col group, 32-col half
        const unsigned char* Bb = smem + SM_B + ngp * 2048 + half * 1024 + lane * 16;

        __syncthreads();                                // buf0 ready

        int buf = 0;
        while (t < ntiles) {
            float acc[4][4][4];
            #pragma unroll
            for (int j = 0; j < 4; j++)
                #pragma unroll
                for (int f = 0; f < 4; f++)
                    #pragma unroll
                    for (int i = 0; i < 4; i++) acc[j][f][i] = 0.0f;

            const unsigned char* A = smem + (buf ? SM_A1 : SM_A0);
            #pragma unroll
            for (int ks = 0; ks < 16; ks++) {
                const int lx = (lane ^ ks) * 16;        // ks-XOR chunk placement
                uint4 a[4];
                #pragma unroll
                for (int j = 0; j < 4; j++)
                    a[j] = *(const uint4*)(A + ks * 2048 + j * 512 + lx);
                uint4 bq[2];
                #pragma unroll
                for (int c = 0; c < 2; c++)
                    bq[c] = *(const uint4*)(Bb + ks * 8192 + c * 512);
                #pragma unroll
                for (int j = 0; j < 4; j++) {
                    #pragma unroll
                    for (int f = 0; f < 4; f++) {
                        const uint4& b = bq[f >> 1];
                        uint32_t r0 = (f & 1) ? b.z : b.x;
                        uint32_t r1 = (f & 1) ? b.w : b.y;
                        asm volatile(
                            "mma.sync.aligned.m16n8k16.row.col.f32.f16.f16.f32 "
                            "{%0,%1,%2,%3}, {%4,%5,%6,%7}, {%8,%9}, {%0,%1,%2,%3};"
                            : "+f"(acc[j][f][0]), "+f"(acc[j][f][1]),
                              "+f"(acc[j][f][2]), "+f"(acc[j][f][3])
                            : "r"(a[j].x), "r"(a[j].y), "r"(a[j].z), "r"(a[j].w),
                              "r"(r0), "r"(r1));
                    }
                }
            }

            // epilogue: sigmoid + permuted STG.128 (4 consecutive floats/lane)
            {
                const int q = lane & 3;
                const size_t rowbase = (size_t)t * MTILE + (lane >> 2);
                #pragma unroll
                for (int j = 0; j < 4; j++) {
                    size_t r0 = rowbase + j * 16;
                    #pragma unroll
                    for (int c = 0; c < 2; c++) {
                        int col = ngp * 64 + 16 * (2 * half + c) + 4 * q;
                        float4 v0, v1;
                        v0.x = sigm(acc[j][2 * c][0]);     v0.y = sigm(acc[j][2 * c][1]);
                        v0.z = sigm(acc[j][2 * c + 1][0]); v0.w = sigm(acc[j][2 * c + 1][1]);
                        v1.x = sigm(acc[j][2 * c][2]);     v1.y = sigm(acc[j][2 * c][3]);
                        v1.z = sigm(acc[j][2 * c + 1][2]); v1.w = sigm(acc[j][2 * c + 1][3]);
                        *(float4*)(out + r0 * NDIM + col)       = v0;
                        *(float4*)(out + (r0 + 8) * NDIM + col) = v1;
                    }
                }
            }

            __syncthreads();    // next buffer staged; current reusable
            buf ^= 1;
            t += (int)gridDim.x;
        }
    }
}

extern "C" void kernel_launch(void* const* d_in, const int* in_sizes, int n_in,
                              void* d_out, int out_size) {
    const float4* xg = (const float4*)d_in[0];   // (B, 64, 4) f32
    const float4* wg = (const float4*)d_in[1];   // (64, 64, 4) f32
    const float4* tg = (const float4*)d_in[2];   // (64, 4) f32
    float* out = (float*)d_out;

    int B = in_sizes[0] / 256;                   // 131072
    int ntiles = B / MTILE;                      // 2048
    int grid = 148;
    if (grid > ntiles) grid = ntiles;

    cudaFuncSetAttribute(gemm_kernel,
                         cudaFuncAttributeMaxDynamicSharedMemorySize, SM_TOTAL);

    build_w<<<32, 256>>>(wg, tg);
    gemm_kernel<<<grid, NTHR, SM_TOTAL>>>(xg, out, ntiles);
}